// round 4
// baseline (speedup 1.0000x reference)
#include <cuda_runtime.h>
#include <cuda_bf16.h>

// Problem constants (match reference)
#define N_NODES 50000
#define N_EDGES 800000
#define N_FEAT  128
#define DIM     64
#define N_GRAPHS 512

// Scratch (device globals — no allocation allowed). 16B-aligned for float4 atomics.
__device__ __align__(16) float g_h[N_NODES * DIM];      // h1 then h2 (reused)
__device__ __align__(16) float g_agg1[N_NODES * DIM];   // scatter result of conv1
__device__ __align__(16) float g_agg2[N_NODES * DIM];   // scatter result of conv2
__device__ __align__(16) float g_pooled[N_GRAPHS * DIM];
__device__ __align__(16) float g_counts[N_GRAPHS];

// ---------------------------------------------------------------------------
// Zero scratch accumulators
// ---------------------------------------------------------------------------
__global__ void zero_kernel() {
    int i = blockIdx.x * blockDim.x + threadIdx.x;
    int n4 = (N_NODES * DIM) / 4;          // 800000 float4 per agg buffer
    if (i < n4) {
        ((float4*)g_agg1)[i] = make_float4(0.f, 0.f, 0.f, 0.f);
        ((float4*)g_agg2)[i] = make_float4(0.f, 0.f, 0.f, 0.f);
    }
    if (i < (N_GRAPHS * DIM) / 4)
        ((float4*)g_pooled)[i] = make_float4(0.f, 0.f, 0.f, 0.f);
    if (i < N_GRAPHS)
        g_counts[i] = 0.f;
}

// ---------------------------------------------------------------------------
// GEMM1: g_h[N,64] = x[N,128] @ W1[128,64]
// Block: 256 threads = 16 rows x 16 col-groups (4 cols each)
// ---------------------------------------------------------------------------
__global__ void gemm1_kernel(const float* __restrict__ x,
                             const float* __restrict__ W1) {
    __shared__ float4 Ws[N_FEAT * 16];   // 128 x 16 float4 = 32KB
    __shared__ float  xs[16 * 129];      // padded to kill bank conflicts

    int tid = threadIdx.x;
    const float4* Wv = (const float4*)W1;
    for (int i = tid; i < N_FEAT * 16; i += 256) Ws[i] = Wv[i];

    int rowBase = blockIdx.x * 16;
    // load 16 rows of x (128 floats each) as float4
    for (int i = tid; i < 16 * 32; i += 256) {
        int r = i >> 5, c4 = i & 31;
        float4 v = ((const float4*)x)[(rowBase + r) * 32 + c4];
        float* p = &xs[r * 129 + c4 * 4];
        p[0] = v.x; p[1] = v.y; p[2] = v.z; p[3] = v.w;
    }
    __syncthreads();

    int r = tid >> 4, cg = tid & 15;
    const float* xr = &xs[r * 129];
    float4 acc = make_float4(0.f, 0.f, 0.f, 0.f);
    #pragma unroll 8
    for (int k = 0; k < N_FEAT; k++) {
        float xv = xr[k];
        float4 w = Ws[k * 16 + cg];
        acc.x += xv * w.x; acc.y += xv * w.y;
        acc.z += xv * w.z; acc.w += xv * w.w;
    }
    ((float4*)g_h)[(rowBase + r) * 16 + cg] = acc;
}

// ---------------------------------------------------------------------------
// GEMM2: g_h[N,64] = relu(g_agg1)[N,64] @ W2[64,64]
// ---------------------------------------------------------------------------
__global__ void gemm2_kernel(const float* __restrict__ W2) {
    __shared__ float4 Ws[DIM * 16];      // 64 x 16 float4 = 16KB
    __shared__ float  xs[16 * 65];

    int tid = threadIdx.x;
    const float4* Wv = (const float4*)W2;
    for (int i = tid; i < DIM * 16; i += 256) Ws[i] = Wv[i];

    int rowBase = blockIdx.x * 16;
    // load 16 rows of agg1 (64 floats each) with fused relu
    for (int i = tid; i < 16 * 16; i += 256) {
        int r = i >> 4, c4 = i & 15;
        float4 v = ((const float4*)g_agg1)[(rowBase + r) * 16 + c4];
        v.x = fmaxf(v.x, 0.f); v.y = fmaxf(v.y, 0.f);
        v.z = fmaxf(v.z, 0.f); v.w = fmaxf(v.w, 0.f);
        float* p = &xs[r * 65 + c4 * 4];
        p[0] = v.x; p[1] = v.y; p[2] = v.z; p[3] = v.w;
    }
    __syncthreads();

    int r = tid >> 4, cg = tid & 15;
    const float* xr = &xs[r * 65];
    float4 acc = make_float4(0.f, 0.f, 0.f, 0.f);
    #pragma unroll 8
    for (int k = 0; k < DIM; k++) {
        float xv = xr[k];
        float4 w = Ws[k * 16 + cg];
        acc.x += xv * w.x; acc.y += xv * w.y;
        acc.z += xv * w.z; acc.w += xv * w.w;
    }
    ((float4*)g_h)[(rowBase + r) * 16 + cg] = acc;
}

// ---------------------------------------------------------------------------
// Edge scatter-add: agg[dst] += h[src], 16 threads (float4 lanes) per edge.
// Native float4 atomicAdd (sm_90+) — emits vector RED.
// Edge indices are INT32 (JAX silently downcasts int64 without x64 mode).
// ---------------------------------------------------------------------------
__global__ void scatter_kernel(int phase,
                               const int* __restrict__ edge_index) {
    const float4* h = (const float4*)g_h;
    float4* agg = (float4*)(phase ? g_agg2 : g_agg1);
    int t = blockIdx.x * blockDim.x + threadIdx.x;
    if (t >= N_EDGES * 16) return;
    int e = t >> 4, c = t & 15;
    int s = edge_index[e];
    int d = edge_index[N_EDGES + e];
    float4 v = h[s * 16 + c];
    atomicAdd(&agg[d * 16 + c], v);
}

// ---------------------------------------------------------------------------
// Segment pooling: pooled[batch[n]] += agg2[n]; counts[batch[n]] += 1
// ---------------------------------------------------------------------------
__global__ void pool_kernel(const int* __restrict__ batch) {
    int t = blockIdx.x * blockDim.x + threadIdx.x;
    if (t >= N_NODES * 16) return;
    int n = t >> 4, c = t & 15;
    int g = batch[n];
    float4 v = ((const float4*)g_agg2)[n * 16 + c];
    atomicAdd(&((float4*)g_pooled)[g * 16 + c], v);
    if (c == 0) atomicAdd(&g_counts[g], 1.0f);
}

// ---------------------------------------------------------------------------
// Final FC + sigmoid: out[g] = sigmoid( (pooled[g]/max(count,1)) . Wfc )
// ---------------------------------------------------------------------------
__global__ void final_kernel(const float* __restrict__ Wfc,
                             float* __restrict__ out) {
    __shared__ float wf[DIM];
    int tid = threadIdx.x;
    if (tid < DIM) wf[tid] = Wfc[tid];
    __syncthreads();
    if (tid >= N_GRAPHS) return;
    float cnt = fmaxf(g_counts[tid], 1.0f);
    float s = 0.f;
    #pragma unroll
    for (int d = 0; d < DIM; d++)
        s += g_pooled[tid * DIM + d] * wf[d];
    s /= cnt;
    out[tid] = 1.0f / (1.0f + expf(-s));
}

// ---------------------------------------------------------------------------
extern "C" void kernel_launch(void* const* d_in, const int* in_sizes, int n_in,
                              void* d_out, int out_size) {
    const float* x    = (const float*)d_in[0];
    const int*   ei   = (const int*)d_in[1];
    const int*   batch= (const int*)d_in[2];
    const float* W1   = (const float*)d_in[3];
    const float* W2   = (const float*)d_in[4];
    const float* Wfc  = (const float*)d_in[5];
    float*       out  = (float*)d_out;

    // zero accumulators: 800000 float4 per agg buffer -> 3125 blocks x 256
    zero_kernel<<<3125, 256>>>();
    // GEMM1: 50000 rows / 16 per block
    gemm1_kernel<<<N_NODES / 16, 256>>>(x, W1);
    // scatter conv1: 800000 edges x 16 lanes / 256
    scatter_kernel<<<(N_EDGES * 16) / 256, 256>>>(0, ei);
    // GEMM2 (relu fused on load)
    gemm2_kernel<<<N_NODES / 16, 256>>>(W2);
    // scatter conv2
    scatter_kernel<<<(N_EDGES * 16) / 256, 256>>>(1, ei);
    // pooling: 50000 nodes x 16 lanes
    pool_kernel<<<(N_NODES * 16 + 255) / 256, 256>>>(batch);
    // FC + sigmoid
    final_kernel<<<1, N_GRAPHS>>>(Wfc, out);
}